// round 4
// baseline (speedup 1.0000x reference)
#include <cuda_runtime.h>
#include <cstdint>

// Gauss-Legendre tables for n = 1..5 (numpy-double -> float32 cast).
__constant__ float XI_TAB[5][5] = {
    { 0.0f, 0.f, 0.f, 0.f, 0.f },
    { -0.5773502691896258f, 0.5773502691896258f, 0.f, 0.f, 0.f },
    { -0.7745966692414834f, 0.0f, 0.7745966692414834f, 0.f, 0.f },
    { -0.8611363115940526f, -0.3399810435848563f, 0.3399810435848563f, 0.8611363115940526f, 0.f },
    { 0.0f, -0.5384693101056831f, 0.5384693101056831f, -0.9061798459386640f, 0.9061798459386640f },
};
__constant__ float W_TAB[5][5] = {
    { 2.0f, 0.f, 0.f, 0.f, 0.f },
    { 1.0f, 1.0f, 0.f, 0.f, 0.f },
    { 0.5555555555555556f, 0.8888888888888889f, 0.5555555555555556f, 0.f, 0.f },
    { 0.3478548451374538f, 0.6521451548625461f, 0.6521451548625461f, 0.3478548451374538f, 0.f },
    { 0.5688888888888889f, 0.4786286704993665f, 0.4786286704993665f, 0.2369268850561891f, 0.2369268850561891f },
};

// Exact reference rounding sequence per Gauss point (no FMA contraction —
// the x_g - x1 cancellation at x1 ~ 4e6 must quantize identically).
template <int G>
__device__ __forceinline__ void eval_elem(float x1, float x2, float v1, float v2,
                                          float* f_int, float* f_xg, float* f_djw)
{
    float dx   = __fsub_rn(x2, x1);
    float detJ = __fmul_rn(dx, 0.5f);
#pragma unroll
    for (int g = 0; g < G; ++g) {
        float xi  = XI_TAB[G - 1][g];
        float w   = W_TAB[G - 1][g];
        float t   = __fmul_rn(__fmul_rn(__fadd_rn(xi, 1.0f), dx), 0.5f);
        float x_g = __fadd_rn(x1, t);
        float num = __fmul_rn(2.0f, __fsub_rn(x_g, x1));
        float ref = __fsub_rn(__fdiv_rn(num, dx), 1.0f);
        float N0  = __fadd_rn(__fmul_rn(-0.5f, ref), 0.5f);
        float N1  = __fadd_rn(__fmul_rn(0.5f, ref), 0.5f);
        f_int[g] = __fadd_rn(__fmul_rn(N0, v1), __fmul_rn(N1, v2));
        f_xg[g]  = x_g;
        f_djw[g] = __fmul_rn(detJ, w);
    }
}

// 4 elements per thread: vectorized conn loads (2x LDG.128), vectorized smem
// staging (STS.128, per-thread 48B-aligned runs, conflict-free: 12t mod 32
// distinct within each store phase), coalesced STG.128 flush.
template <int G, int BLOCK, int EPT>
__global__ void __launch_bounds__(BLOCK) meshnn1d_kernel(
    const float* __restrict__ coords,
    const float* __restrict__ vals,
    const int*   __restrict__ conn,    // [E,2] int32, 1-based
    float* __restrict__ out,           // [3, E, G] : interpol | x_g | detJ_w
    int E)
{
    constexpr int ELEM_BLOCK = BLOCK * EPT;
    constexpr int FPT        = EPT * G;          // floats per thread per section
    __shared__ float s_buf[3][ELEM_BLOCK * G];

    const int tid        = threadIdx.x;
    const int blockStart = blockIdx.x * ELEM_BLOCK;
    const int nElem      = min(ELEM_BLOCK, E - blockStart);  // elements this block
    const int e0         = tid * EPT;                        // local element base

    if (e0 + EPT <= nElem) {
        // --- full fast path: 4 elements ---
        const int4* c4 = reinterpret_cast<const int4*>(conn) +
                         ((size_t)(blockStart + e0) >> 1);
        int4 ca = c4[0];   // elements e0, e0+1
        int4 cb = c4[1];   // elements e0+2, e0+3

        int i1[EPT] = { ca.x - 1, ca.z - 1, cb.x - 1, cb.z - 1 };
        int i2[EPT] = { ca.y - 1, ca.w - 1, cb.y - 1, cb.w - 1 };

        float x1[EPT], x2[EPT], v1[EPT], v2[EPT];
#pragma unroll
        for (int k = 0; k < EPT; ++k) { x1[k] = coords[i1[k]]; x2[k] = coords[i2[k]]; }
#pragma unroll
        for (int k = 0; k < EPT; ++k) { v1[k] = vals[i1[k]];   v2[k] = vals[i2[k]]; }

        float f_int[FPT], f_xg[FPT], f_djw[FPT];
#pragma unroll
        for (int k = 0; k < EPT; ++k)
            eval_elem<G>(x1[k], x2[k], v1[k], v2[k],
                         f_int + k * G, f_xg + k * G, f_djw + k * G);

        // vectorized staging: FPT is a multiple of 4 for EPT=4, any G
        static_assert(FPT % 4 == 0, "FPT must be divisible by 4");
        float4* d0 = reinterpret_cast<float4*>(&s_buf[0][e0 * G]);
        float4* d1 = reinterpret_cast<float4*>(&s_buf[1][e0 * G]);
        float4* d2 = reinterpret_cast<float4*>(&s_buf[2][e0 * G]);
#pragma unroll
        for (int j = 0; j < FPT / 4; ++j) {
            d0[j] = make_float4(f_int[4*j], f_int[4*j+1], f_int[4*j+2], f_int[4*j+3]);
            d1[j] = make_float4(f_xg[4*j],  f_xg[4*j+1],  f_xg[4*j+2],  f_xg[4*j+3]);
            d2[j] = make_float4(f_djw[4*j], f_djw[4*j+1], f_djw[4*j+2], f_djw[4*j+3]);
        }
    } else if (e0 < nElem) {
        // --- tail: scalar per element ---
        for (int k = 0; k < EPT && e0 + k < nElem; ++k) {
            int e = blockStart + e0 + k;
            int2 c = reinterpret_cast<const int2*>(conn)[e];
            int i1 = c.x - 1, i2 = c.y - 1;
            float f_int[G], f_xg[G], f_djw[G];
            eval_elem<G>(coords[i1], coords[i2], vals[i1], vals[i2], f_int, f_xg, f_djw);
#pragma unroll
            for (int g = 0; g < G; ++g) {
                s_buf[0][(e0 + k) * G + g] = f_int[g];
                s_buf[1][(e0 + k) * G + g] = f_xg[g];
                s_buf[2][(e0 + k) * G + g] = f_djw[g];
            }
        }
    }
    __syncthreads();

    const size_t EG   = (size_t)E * G;
    const size_t base = (size_t)blockStart * G;
    const int nFloats = nElem * G;

    if (nElem == ELEM_BLOCK) {
        constexpr int NV = ELEM_BLOCK * G / 4;
#pragma unroll
        for (int sec = 0; sec < 3; ++sec) {
            const float4* src = reinterpret_cast<const float4*>(&s_buf[sec][0]);
            size_t off = (size_t)sec * EG + base;
            if ((off & 3) == 0) {
                float4* dst = reinterpret_cast<float4*>(out + off);
#pragma unroll 2
                for (int i = tid; i < NV; i += BLOCK) dst[i] = src[i];
            } else {
                for (int i = tid; i < ELEM_BLOCK * G; i += BLOCK)
                    out[off + i] = s_buf[sec][i];
            }
        }
    } else {
#pragma unroll
        for (int sec = 0; sec < 3; ++sec) {
            size_t off = (size_t)sec * EG + base;
            for (int i = tid; i < nFloats; i += BLOCK)
                out[off + i] = s_buf[sec][i];
        }
    }
}

template <int G>
static void launch(const float* coords, const float* vals, const int* conn,
                   float* out, int E)
{
    constexpr int BLOCK = 256;
    constexpr int EPT   = 4;
    int blocks = (E + BLOCK * EPT - 1) / (BLOCK * EPT);
    meshnn1d_kernel<G, BLOCK, EPT><<<blocks, BLOCK>>>(coords, vals, conn, out, E);
}

extern "C" void kernel_launch(void* const* d_in, const int* in_sizes, int n_in,
                              void* d_out, int out_size)
{
    const float* coords = (const float*)d_in[0];
    const float* vals   = (const float*)d_in[1];
    const int*   conn   = (const int*)d_in[2];
    float*       out    = (float*)d_out;

    int E = in_sizes[2] / 2;
    int G = (E > 0) ? (int)((long long)out_size / (3LL * E)) : 3;
    if (G < 1) G = 1;
    if (G > 5) G = 5;

    switch (G) {
        case 1: launch<1>(coords, vals, conn, out, E); break;
        case 2: launch<2>(coords, vals, conn, out, E); break;
        case 3: launch<3>(coords, vals, conn, out, E); break;
        case 4: launch<4>(coords, vals, conn, out, E); break;
        case 5: launch<5>(coords, vals, conn, out, E); break;
    }
}